// round 16
// baseline (speedup 1.0000x reference)
#include <cuda_runtime.h>
#include <cuda_fp16.h>
#include <cuda_bf16.h>
#include <cstddef>
#include <cstdint>

// Problem constants (fixed by the dataset)
#define M_NODES 100000
#define K_FIN   512
#define N_FOUT  256
#define N_EDGES 3200000

// GEMM m-chunking for convert/GEMM pipelining
#define MBLOCKS_TOTAL 782          // ceil(100000/128)
#define MBLOCKS_C0    391
#define ROWS_C0       (MBLOCKS_C0 * 128)   // 50048

// ---------------------------------------------------------------------------
// Static device scratch (no allocations allowed anywhere)
// ---------------------------------------------------------------------------
__device__ __half g_xh[(size_t)M_NODES * K_FIN];       // x in fp16 (102.4 MB)
__device__ __half g_wh[K_FIN * N_FOUT];                // W in fp16 (0.25 MB)
__device__ __half g_h[(size_t)M_NODES * N_FOUT];       // h = x @ W  (51.2 MB)
__device__ int    g_row_count[M_NODES];
__device__ int    g_row_start[M_NODES + 1];
__device__ int    g_row_fill[M_NODES];
__device__ int2   g_csr_cv[N_EDGES];                   // packed (col, val-bits)

// ---------------------------------------------------------------------------
// fp16 MMA + ldmatrix + cp.async helpers
// ---------------------------------------------------------------------------
__device__ __forceinline__ void mma_f16(float* c, const uint32_t* a,
                                        uint32_t b0, uint32_t b1) {
    asm volatile(
        "mma.sync.aligned.m16n8k16.row.col.f32.f16.f16.f32 "
        "{%0,%1,%2,%3}, {%4,%5,%6,%7}, {%8,%9}, {%0,%1,%2,%3};\n"
        : "+f"(c[0]), "+f"(c[1]), "+f"(c[2]), "+f"(c[3])
        : "r"(a[0]), "r"(a[1]), "r"(a[2]), "r"(a[3]), "r"(b0), "r"(b1));
}

#define LDSM_X4(r0, r1, r2, r3, addr)                                        \
    asm volatile("ldmatrix.sync.aligned.m8n8.x4.shared.b16 {%0,%1,%2,%3},[%4];" \
                 : "=r"(r0), "=r"(r1), "=r"(r2), "=r"(r3) : "r"(addr))

#define LDSM_X4_T(r0, r1, r2, r3, addr)                                      \
    asm volatile("ldmatrix.sync.aligned.m8n8.x4.trans.shared.b16 {%0,%1,%2,%3},[%4];" \
                 : "=r"(r0), "=r"(r1), "=r"(r2), "=r"(r3) : "r"(addr))

__device__ __forceinline__ void cp_async16(uint32_t dst_smem, const void* src) {
    asm volatile("cp.async.cg.shared.global [%0], [%1], 16;"
                 :: "r"(dst_smem), "l"(src));
}
#define CP_COMMIT()  asm volatile("cp.async.commit_group;")
#define CP_WAIT(n)   asm volatile("cp.async.wait_group %0;" :: "n"(n))

// ---------------------------------------------------------------------------
// Conversion kernels: f32 -> f16
// ---------------------------------------------------------------------------
__global__ __launch_bounds__(256)
void convert_x_chunk_kernel(const float* __restrict__ in, __half* __restrict__ out,
                            size_t elem4_off, size_t n_elem4)
{
    size_t idx = (size_t)blockIdx.x * blockDim.x + threadIdx.x;
    size_t stride = (size_t)gridDim.x * blockDim.x;
    __half2* out2 = reinterpret_cast<__half2*>(out);
    for (size_t i = idx; i < n_elem4; i += stride) {
        size_t g = elem4_off + i;
        float4 v = reinterpret_cast<const float4*>(in)[g];
        out2[2 * g + 0] = __floats2half2_rn(v.x, v.y);
        out2[2 * g + 1] = __floats2half2_rn(v.z, v.w);
    }
}

__global__ __launch_bounds__(256)
void convert_w_kernel(const float* __restrict__ in, __half* __restrict__ out)
{
    const int total4 = K_FIN * N_FOUT / 4;
    int idx = blockIdx.x * blockDim.x + threadIdx.x;
    int stride = gridDim.x * blockDim.x;
    __half2* out2 = reinterpret_cast<__half2*>(out);
    for (int i = idx; i < total4; i += stride) {
        float4 v = reinterpret_cast<const float4*>(in)[i];
        out2[2 * i + 0] = __floats2half2_rn(v.x, v.y);
        out2[2 * i + 1] = __floats2half2_rn(v.z, v.w);
    }
}

// ---------------------------------------------------------------------------
// Kernel 1: fp16 HMMA GEMM with cp.async double-buffered smem pipeline.
// BM=128, BN=128, BK=64; 256 threads = 8 warps (4 m x 2 n), warp tile 32x64.
// Parameterized by m-block and n-block offset (column-half splitting).
// ---------------------------------------------------------------------------
#define AS_HALVES (128 * 72)
#define BS_HALVES (64 * 136)
#define SMEM_BYTES ((2 * AS_HALVES + 2 * BS_HALVES) * 2)

__global__ __launch_bounds__(256, 2)
void hgemm_kernel(const __half* __restrict__ A,   // [M, 512] f16
                  const __half* __restrict__ W,   // [512, 256] f16
                  __half* __restrict__ C,         // [M, 256] f16
                  int m_off, int n_off)           // block offsets
{
    extern __shared__ __half smem[];
    __half* As0 = smem;
    __half* As1 = As0 + AS_HALVES;
    __half* Bs0 = As1 + AS_HALVES;
    __half* Bs1 = Bs0 + BS_HALVES;

    const int tid  = threadIdx.x;
    const int lane = tid & 31;
    const int warp = tid >> 5;
    const int gid  = lane >> 2;
    const int tig  = lane & 3;
    const int wm   = (warp & 3) * 32;
    const int wn   = (warp >> 2) * 64;
    const int bm   = (blockIdx.x + m_off) * 128;
    const int bn   = (blockIdx.y + n_off) * 128;

    const int li   = lane >> 3;
    const int l7   = lane & 7;
    const int frow = ((li & 1) << 3) + l7;
    const int fcol = (li >> 1) << 3;

    const uint32_t as_base[2] = {
        (uint32_t)__cvta_generic_to_shared(As0),
        (uint32_t)__cvta_generic_to_shared(As1) };
    const uint32_t bs_base[2] = {
        (uint32_t)__cvta_generic_to_shared(Bs0),
        (uint32_t)__cvta_generic_to_shared(Bs1) };

    const int a_row = tid >> 2;
    const int a_h0  = (tid & 3) << 4;
    const int b_kr  = tid >> 3;
    const int b_h0  = (tid & 7) << 4;

    int gma0 = bm + a_row;       if (gma0 >= M_NODES) gma0 = 0;
    int gma1 = bm + a_row + 64;  if (gma1 >= M_NODES) gma1 = 0;

    auto stage = [&](int buf, int k0) {
        const __half* ap0 = A + (size_t)gma0 * K_FIN + k0 + a_h0;
        const __half* ap1 = A + (size_t)gma1 * K_FIN + k0 + a_h0;
        uint32_t d0 = as_base[buf] + ((a_row)      * 72 + a_h0) * 2;
        uint32_t d1 = as_base[buf] + ((a_row + 64) * 72 + a_h0) * 2;
        cp_async16(d0,      ap0);
        cp_async16(d0 + 16, ap0 + 8);
        cp_async16(d1,      ap1);
        cp_async16(d1 + 16, ap1 + 8);
        const __half* bp0 = W + (size_t)(k0 + b_kr)      * N_FOUT + bn + b_h0;
        const __half* bp1 = W + (size_t)(k0 + b_kr + 32) * N_FOUT + bn + b_h0;
        uint32_t e0 = bs_base[buf] + ((b_kr)      * 136 + b_h0) * 2;
        uint32_t e1 = bs_base[buf] + ((b_kr + 32) * 136 + b_h0) * 2;
        cp_async16(e0,      bp0);
        cp_async16(e0 + 16, bp0 + 8);
        cp_async16(e1,      bp1);
        cp_async16(e1 + 16, bp1 + 8);
    };

    float acc[2][8][4];
#pragma unroll
    for (int mt = 0; mt < 2; mt++)
#pragma unroll
        for (int nt = 0; nt < 8; nt++)
#pragma unroll
            for (int i = 0; i < 4; i++) acc[mt][nt][i] = 0.f;

    stage(0, 0);
    CP_COMMIT();

    const int NTILES = K_FIN / 64;   // 8
#pragma unroll 1
    for (int kt = 0; kt < NTILES; kt++) {
        const int buf = kt & 1;
        if (kt + 1 < NTILES) {
            stage(buf ^ 1, (kt + 1) * 64);
            CP_COMMIT();
            CP_WAIT(1);
        } else {
            CP_WAIT(0);
        }
        __syncthreads();

#pragma unroll
        for (int ks = 0; ks < 4; ks++) {
            const int kk = ks * 16;
            uint32_t a[2][4];
#pragma unroll
            for (int mt = 0; mt < 2; mt++) {
                uint32_t addr = as_base[buf] +
                    (((wm + mt * 16 + frow) * 72) + kk + fcol) * 2;
                LDSM_X4(a[mt][0], a[mt][1], a[mt][2], a[mt][3], addr);
            }
            uint32_t b[8][2];
#pragma unroll
            for (int np = 0; np < 4; np++) {
                uint32_t addr = bs_base[buf] +
                    (((kk + frow) * 136) + wn + np * 16 + fcol) * 2;
                uint32_t r0, r1, r2, r3;
                LDSM_X4_T(r0, r1, r2, r3, addr);
                b[np * 2 + 0][0] = r0;
                b[np * 2 + 0][1] = r1;
                b[np * 2 + 1][0] = r2;
                b[np * 2 + 1][1] = r3;
            }
#pragma unroll
            for (int mt = 0; mt < 2; mt++)
#pragma unroll
                for (int nt = 0; nt < 8; nt++)
                    mma_f16(acc[mt][nt], a[mt], b[nt][0], b[nt][1]);
        }
        __syncthreads();
    }

#pragma unroll
    for (int mt = 0; mt < 2; mt++) {
#pragma unroll
        for (int nt = 0; nt < 8; nt++) {
            int r0 = bm + wm + mt * 16 + gid;
            int cc = bn + wn + nt * 8 + 2 * tig;
            if (r0 < M_NODES)
                *reinterpret_cast<__half2*>(&C[(size_t)r0 * N_FOUT + cc]) =
                    __floats2half2_rn(acc[mt][nt][0], acc[mt][nt][1]);
            int r1 = r0 + 8;
            if (r1 < M_NODES)
                *reinterpret_cast<__half2*>(&C[(size_t)r1 * N_FOUT + cc]) =
                    __floats2half2_rn(acc[mt][nt][2], acc[mt][nt][3]);
        }
    }
}

// ---------------------------------------------------------------------------
// CSR construction: count -> scan -> scatter (packed int2 payload)
// ---------------------------------------------------------------------------
__global__ __launch_bounds__(256)
void count_kernel(const int* __restrict__ rows)
{
    int idx = blockIdx.x * blockDim.x + threadIdx.x;
    int stride = gridDim.x * blockDim.x;
    for (int e = idx; e < N_EDGES; e += stride) {
        atomicAdd(&g_row_count[rows[e]], 1);
    }
}

#define SCAN_T 1024
__global__ __launch_bounds__(SCAN_T)
void scan_kernel()
{
    __shared__ int part[SCAN_T];
    const int chunk = (M_NODES + SCAN_T - 1) / SCAN_T;
    int t = threadIdx.x;
    int begin = t * chunk;
    int end   = begin + chunk;
    if (end > M_NODES) end = M_NODES;
    if (begin > M_NODES) begin = M_NODES;

    int s = 0;
    for (int i = begin; i < end; i++) s += g_row_count[i];
    part[t] = s;
    __syncthreads();

    for (int off = 1; off < SCAN_T; off <<= 1) {
        int v = 0;
        if (t >= off) v = part[t - off];
        __syncthreads();
        part[t] += v;
        __syncthreads();
    }

    int run = (t == 0) ? 0 : part[t - 1];
    for (int i = begin; i < end; i++) {
        g_row_start[i] = run;
        run += g_row_count[i];
    }
    if (t == SCAN_T - 1) g_row_start[M_NODES] = run;
}

__global__ __launch_bounds__(256)
void scatter_kernel(const int*   __restrict__ rows,
                    const int*   __restrict__ cols,
                    const float* __restrict__ vals)
{
    int idx = blockIdx.x * blockDim.x + threadIdx.x;
    int stride = gridDim.x * blockDim.x;
    for (int e = idx; e < N_EDGES; e += stride) {
        int r = rows[e];
        int pos = g_row_start[r] + atomicAdd(&g_row_fill[r], 1);
        g_csr_cv[pos] = make_int2(cols[e], __float_as_int(vals[e]));
    }
}

// ---------------------------------------------------------------------------
// Kernel 2: CSR SpMM + fused ReLU over a 128-column half.
// One warp per row; each lane owns 4 consecutive cols (LDG.64 per edge).
// ---------------------------------------------------------------------------
__global__ __launch_bounds__(256)
void spmm_csr_half_kernel(const __half* __restrict__ h,
                          float*        __restrict__ out,
                          int n_off)    // 0 or 128
{
    int warp_global = (blockIdx.x * blockDim.x + threadIdx.x) >> 5;
    int lane = threadIdx.x & 31;
    if (warp_global >= M_NODES) return;

    int row = warp_global;
    int s = g_row_start[row];
    int e = g_row_start[row + 1];

    const __half* hh = h + n_off + lane * 4;   // this lane's 4 cols

    float acc[4];
#pragma unroll
    for (int i = 0; i < 4; i++) acc[i] = 0.f;

    int i = s;
    for (; i + 4 <= e; i += 4) {
        int2 cv0 = g_csr_cv[i + 0];
        int2 cv1 = g_csr_cv[i + 1];
        int2 cv2 = g_csr_cv[i + 2];
        int2 cv3 = g_csr_cv[i + 3];
        float v0 = __int_as_float(cv0.y), v1 = __int_as_float(cv1.y);
        float v2 = __int_as_float(cv2.y), v3 = __int_as_float(cv3.y);
        uint2 p0 = __ldg(reinterpret_cast<const uint2*>(hh + (size_t)cv0.x * N_FOUT));
        uint2 p1 = __ldg(reinterpret_cast<const uint2*>(hh + (size_t)cv1.x * N_FOUT));
        uint2 p2 = __ldg(reinterpret_cast<const uint2*>(hh + (size_t)cv2.x * N_FOUT));
        uint2 p3 = __ldg(reinterpret_cast<const uint2*>(hh + (size_t)cv3.x * N_FOUT));
        const __half2* q0 = reinterpret_cast<const __half2*>(&p0);
        const __half2* q1 = reinterpret_cast<const __half2*>(&p1);
        const __half2* q2 = reinterpret_cast<const __half2*>(&p2);
        const __half2* q3 = reinterpret_cast<const __half2*>(&p3);
#pragma unroll
        for (int j = 0; j < 2; j++) {
            float2 f0 = __half22float2(q0[j]);
            float2 f1 = __half22float2(q1[j]);
            float2 f2 = __half22float2(q2[j]);
            float2 f3 = __half22float2(q3[j]);
            acc[2 * j + 0] += v0 * f0.x + v1 * f1.x + v2 * f2.x + v3 * f3.x;
            acc[2 * j + 1] += v0 * f0.y + v1 * f1.y + v2 * f2.y + v3 * f3.y;
        }
    }
    for (; i < e; i++) {
        int2 cv = g_csr_cv[i];
        float v = __int_as_float(cv.y);
        uint2 p = __ldg(reinterpret_cast<const uint2*>(hh + (size_t)cv.x * N_FOUT));
        const __half2* q = reinterpret_cast<const __half2*>(&p);
#pragma unroll
        for (int j = 0; j < 2; j++) {
            float2 f = __half22float2(q[j]);
            acc[2 * j + 0] += v * f.x;
            acc[2 * j + 1] += v * f.y;
        }
    }

    float* orow = out + (size_t)row * N_FOUT + n_off + lane * 4;
    *reinterpret_cast<float4*>(orow) =
        make_float4(fmaxf(acc[0], 0.f), fmaxf(acc[1], 0.f),
                    fmaxf(acc[2], 0.f), fmaxf(acc[3], 0.f));
}

// ---------------------------------------------------------------------------
// Launch graph:
//  s1: conv_c0 -> GEMM(c0,n0) -> GEMM(c1,n0) -> [join CSR] SpMM(n0) -> [n1 done] SpMM(n1)
//  s2: convert_w, CSR build
//  s3: conv_c1
//  s4: GEMM(c0,n1) -> GEMM(c1,n1)   (overlaps SpMM(n0))
// ---------------------------------------------------------------------------
extern "C" void kernel_launch(void* const* d_in, const int* in_sizes, int n_in,
                              void* d_out, int out_size)
{
    const float* x        = (const float*)d_in[0];
    const int*   adj_rows = (const int*)  d_in[1];
    const int*   adj_cols = (const int*)  d_in[2];
    const float* adj_vals = (const float*)d_in[3];
    const float* weight   = (const float*)d_in[4];
    float*       out      = (float*)d_out;

    __half* xh = nullptr;
    __half* wh = nullptr;
    __half* h  = nullptr;
    int*    row_count = nullptr;
    int*    row_fill  = nullptr;
    cudaGetSymbolAddress((void**)&xh, g_xh);
    cudaGetSymbolAddress((void**)&wh, g_wh);
    cudaGetSymbolAddress((void**)&h,  g_h);
    cudaGetSymbolAddress((void**)&row_count, g_row_count);
    cudaGetSymbolAddress((void**)&row_fill, g_row_fill);

    static cudaStream_t s2 = nullptr, s3 = nullptr, s4 = nullptr;
    static cudaEvent_t ev_fork = nullptr, ev_join = nullptr, ev_w = nullptr,
                       ev_c0 = nullptr, ev_c2 = nullptr, ev_n1 = nullptr;
    if (s2 == nullptr) {
        cudaStreamCreateWithFlags(&s2, cudaStreamNonBlocking);
        cudaStreamCreateWithFlags(&s3, cudaStreamNonBlocking);
        cudaStreamCreateWithFlags(&s4, cudaStreamNonBlocking);
        cudaEventCreateWithFlags(&ev_fork, cudaEventDisableTiming);
        cudaEventCreateWithFlags(&ev_join, cudaEventDisableTiming);
        cudaEventCreateWithFlags(&ev_w, cudaEventDisableTiming);
        cudaEventCreateWithFlags(&ev_c0, cudaEventDisableTiming);
        cudaEventCreateWithFlags(&ev_c2, cudaEventDisableTiming);
        cudaEventCreateWithFlags(&ev_n1, cudaEventDisableTiming);
        cudaFuncSetAttribute(hgemm_kernel,
                             cudaFuncAttributeMaxDynamicSharedMemorySize,
                             SMEM_BYTES);
    }

    // ---- fork ----
    cudaEventRecord(ev_fork, 0);
    cudaStreamWaitEvent(s2, ev_fork, 0);
    cudaStreamWaitEvent(s3, ev_fork, 0);

    // s2: convert_w then CSR build
    convert_w_kernel<<<64, 256, 0, s2>>>(weight, wh);
    cudaEventRecord(ev_w, s2);
    cudaMemsetAsync(row_count, 0, M_NODES * sizeof(int), s2);
    cudaMemsetAsync(row_fill,  0, M_NODES * sizeof(int), s2);
    count_kernel<<<2048, 256, 0, s2>>>(adj_rows);
    scan_kernel<<<1, SCAN_T, 0, s2>>>();
    scatter_kernel<<<2048, 256, 0, s2>>>(adj_rows, adj_cols, adj_vals);
    cudaEventRecord(ev_join, s2);

    // s3: convert x chunk1
    const size_t e4_c0 = (size_t)ROWS_C0 * K_FIN / 4;
    const size_t e4_total = (size_t)M_NODES * K_FIN / 4;
    convert_x_chunk_kernel<<<1024, 256, 0, s3>>>(x, xh, e4_c0, e4_total - e4_c0);
    cudaEventRecord(ev_c2, s3);

    // s1: convert x chunk0
    convert_x_chunk_kernel<<<1024, 256>>>(x, xh, 0, e4_c0);
    cudaEventRecord(ev_c0, 0);

    // s4: GEMM column-half n1 (overlaps with s1's n0 GEMM + SpMM(n0))
    cudaStreamWaitEvent(s4, ev_c0, 0);
    cudaStreamWaitEvent(s4, ev_w, 0);
    dim3 g0(MBLOCKS_C0, 1);
    dim3 g1(MBLOCKS_TOTAL - MBLOCKS_C0, 1);
    hgemm_kernel<<<g0, 256, SMEM_BYTES, s4>>>(xh, wh, h, 0, 1);
    cudaStreamWaitEvent(s4, ev_c2, 0);
    hgemm_kernel<<<g1, 256, SMEM_BYTES, s4>>>(xh, wh, h, MBLOCKS_C0, 1);
    cudaEventRecord(ev_n1, s4);

    // s1: GEMM column-half n0
    cudaStreamWaitEvent(0, ev_w, 0);
    hgemm_kernel<<<g0, 256, SMEM_BYTES>>>(xh, wh, h, 0, 0);
    cudaStreamWaitEvent(0, ev_c2, 0);
    hgemm_kernel<<<g1, 256, SMEM_BYTES>>>(xh, wh, h, MBLOCKS_C0, 0);

    // s1: SpMM(n0) once CSR ready; SpMM(n1) once GEMM n1 done
    cudaStreamWaitEvent(0, ev_join, 0);
    int nblocks = (M_NODES * 32 + 255) / 256;
    spmm_csr_half_kernel<<<nblocks, 256>>>(h, out, 0);
    cudaStreamWaitEvent(0, ev_n1, 0);
    spmm_csr_half_kernel<<<nblocks, 256>>>(h, out, 128);
}

// round 17
// speedup vs baseline: 1.0313x; 1.0313x over previous
#include <cuda_runtime.h>
#include <cuda_fp16.h>
#include <cuda_bf16.h>
#include <cstddef>
#include <cstdint>

// Problem constants (fixed by the dataset)
#define M_NODES 100000
#define K_FIN   512
#define N_FOUT  256
#define N_EDGES 3200000

// GEMM m-chunking for convert/GEMM pipelining (3 chunks)
#define MBLOCKS_TOTAL 782          // ceil(100000/128)
#define MB0 262
#define MB1 262
#define MB2 258
#define ROWS0 (MB0 * 128)                  // 33536
#define ROWS1 (MB1 * 128)                  // 33536

// ---------------------------------------------------------------------------
// Static device scratch (no allocations allowed anywhere)
// ---------------------------------------------------------------------------
__device__ __half g_xh[(size_t)M_NODES * K_FIN];       // x in fp16 (102.4 MB)
__device__ __half g_wh[K_FIN * N_FOUT];                // W in fp16 (0.25 MB)
__device__ __half g_h[(size_t)M_NODES * N_FOUT];       // h = x @ W  (51.2 MB)
__device__ int    g_row_count[M_NODES];
__device__ int    g_row_start[M_NODES + 1];
__device__ int    g_row_fill[M_NODES];
__device__ int2   g_csr_cv[N_EDGES];                   // packed (col, val-bits)

// ---------------------------------------------------------------------------
// fp16 MMA + ldmatrix + cp.async helpers
// ---------------------------------------------------------------------------
__device__ __forceinline__ void mma_f16(float* c, const uint32_t* a,
                                        uint32_t b0, uint32_t b1) {
    asm volatile(
        "mma.sync.aligned.m16n8k16.row.col.f32.f16.f16.f32 "
        "{%0,%1,%2,%3}, {%4,%5,%6,%7}, {%8,%9}, {%0,%1,%2,%3};\n"
        : "+f"(c[0]), "+f"(c[1]), "+f"(c[2]), "+f"(c[3])
        : "r"(a[0]), "r"(a[1]), "r"(a[2]), "r"(a[3]), "r"(b0), "r"(b1));
}

#define LDSM_X4(r0, r1, r2, r3, addr)                                        \
    asm volatile("ldmatrix.sync.aligned.m8n8.x4.shared.b16 {%0,%1,%2,%3},[%4];" \
                 : "=r"(r0), "=r"(r1), "=r"(r2), "=r"(r3) : "r"(addr))

#define LDSM_X4_T(r0, r1, r2, r3, addr)                                      \
    asm volatile("ldmatrix.sync.aligned.m8n8.x4.trans.shared.b16 {%0,%1,%2,%3},[%4];" \
                 : "=r"(r0), "=r"(r1), "=r"(r2), "=r"(r3) : "r"(addr))

__device__ __forceinline__ void cp_async16(uint32_t dst_smem, const void* src) {
    asm volatile("cp.async.cg.shared.global [%0], [%1], 16;"
                 :: "r"(dst_smem), "l"(src));
}
#define CP_COMMIT()  asm volatile("cp.async.commit_group;")
#define CP_WAIT(n)   asm volatile("cp.async.wait_group %0;" :: "n"(n))

// ---------------------------------------------------------------------------
// Conversion kernels: f32 -> f16
// ---------------------------------------------------------------------------
__global__ __launch_bounds__(256)
void convert_x_chunk_kernel(const float* __restrict__ in, __half* __restrict__ out,
                            size_t elem4_off, size_t n_elem4)
{
    size_t idx = (size_t)blockIdx.x * blockDim.x + threadIdx.x;
    size_t stride = (size_t)gridDim.x * blockDim.x;
    __half2* out2 = reinterpret_cast<__half2*>(out);
    for (size_t i = idx; i < n_elem4; i += stride) {
        size_t g = elem4_off + i;
        float4 v = reinterpret_cast<const float4*>(in)[g];
        out2[2 * g + 0] = __floats2half2_rn(v.x, v.y);
        out2[2 * g + 1] = __floats2half2_rn(v.z, v.w);
    }
}

__global__ __launch_bounds__(256)
void convert_w_kernel(const float* __restrict__ in, __half* __restrict__ out)
{
    const int total4 = K_FIN * N_FOUT / 4;
    int idx = blockIdx.x * blockDim.x + threadIdx.x;
    int stride = gridDim.x * blockDim.x;
    __half2* out2 = reinterpret_cast<__half2*>(out);
    for (int i = idx; i < total4; i += stride) {
        float4 v = reinterpret_cast<const float4*>(in)[i];
        out2[2 * i + 0] = __floats2half2_rn(v.x, v.y);
        out2[2 * i + 1] = __floats2half2_rn(v.z, v.w);
    }
}

// ---------------------------------------------------------------------------
// Kernel 1: fp16 HMMA GEMM with cp.async double-buffered smem pipeline.
// BM=128, BN=128, BK=64; 256 threads = 8 warps (4 m x 2 n), warp tile 32x64.
// ---------------------------------------------------------------------------
#define AS_HALVES (128 * 72)
#define BS_HALVES (64 * 136)
#define SMEM_BYTES ((2 * AS_HALVES + 2 * BS_HALVES) * 2)

__global__ __launch_bounds__(256, 2)
void hgemm_kernel(const __half* __restrict__ A,   // [M, 512] f16
                  const __half* __restrict__ W,   // [512, 256] f16
                  __half* __restrict__ C,         // [M, 256] f16
                  int m_off)                      // m-block offset
{
    extern __shared__ __half smem[];
    __half* As0 = smem;
    __half* As1 = As0 + AS_HALVES;
    __half* Bs0 = As1 + AS_HALVES;
    __half* Bs1 = Bs0 + BS_HALVES;

    const int tid  = threadIdx.x;
    const int lane = tid & 31;
    const int warp = tid >> 5;
    const int gid  = lane >> 2;
    const int tig  = lane & 3;
    const int wm   = (warp & 3) * 32;
    const int wn   = (warp >> 2) * 64;
    const int bm   = (blockIdx.x + m_off) * 128;
    const int bn   = blockIdx.y * 128;

    const int li   = lane >> 3;
    const int l7   = lane & 7;
    const int frow = ((li & 1) << 3) + l7;
    const int fcol = (li >> 1) << 3;

    const uint32_t as_base[2] = {
        (uint32_t)__cvta_generic_to_shared(As0),
        (uint32_t)__cvta_generic_to_shared(As1) };
    const uint32_t bs_base[2] = {
        (uint32_t)__cvta_generic_to_shared(Bs0),
        (uint32_t)__cvta_generic_to_shared(Bs1) };

    const int a_row = tid >> 2;
    const int a_h0  = (tid & 3) << 4;
    const int b_kr  = tid >> 3;
    const int b_h0  = (tid & 7) << 4;

    int gma0 = bm + a_row;       if (gma0 >= M_NODES) gma0 = 0;
    int gma1 = bm + a_row + 64;  if (gma1 >= M_NODES) gma1 = 0;

    auto stage = [&](int buf, int k0) {
        const __half* ap0 = A + (size_t)gma0 * K_FIN + k0 + a_h0;
        const __half* ap1 = A + (size_t)gma1 * K_FIN + k0 + a_h0;
        uint32_t d0 = as_base[buf] + ((a_row)      * 72 + a_h0) * 2;
        uint32_t d1 = as_base[buf] + ((a_row + 64) * 72 + a_h0) * 2;
        cp_async16(d0,      ap0);
        cp_async16(d0 + 16, ap0 + 8);
        cp_async16(d1,      ap1);
        cp_async16(d1 + 16, ap1 + 8);
        const __half* bp0 = W + (size_t)(k0 + b_kr)      * N_FOUT + bn + b_h0;
        const __half* bp1 = W + (size_t)(k0 + b_kr + 32) * N_FOUT + bn + b_h0;
        uint32_t e0 = bs_base[buf] + ((b_kr)      * 136 + b_h0) * 2;
        uint32_t e1 = bs_base[buf] + ((b_kr + 32) * 136 + b_h0) * 2;
        cp_async16(e0,      bp0);
        cp_async16(e0 + 16, bp0 + 8);
        cp_async16(e1,      bp1);
        cp_async16(e1 + 16, bp1 + 8);
    };

    float acc[2][8][4];
#pragma unroll
    for (int mt = 0; mt < 2; mt++)
#pragma unroll
        for (int nt = 0; nt < 8; nt++)
#pragma unroll
            for (int i = 0; i < 4; i++) acc[mt][nt][i] = 0.f;

    stage(0, 0);
    CP_COMMIT();

    const int NTILES = K_FIN / 64;   // 8
#pragma unroll 1
    for (int kt = 0; kt < NTILES; kt++) {
        const int buf = kt & 1;
        if (kt + 1 < NTILES) {
            stage(buf ^ 1, (kt + 1) * 64);
            CP_COMMIT();
            CP_WAIT(1);
        } else {
            CP_WAIT(0);
        }
        __syncthreads();

#pragma unroll
        for (int ks = 0; ks < 4; ks++) {
            const int kk = ks * 16;
            uint32_t a[2][4];
#pragma unroll
            for (int mt = 0; mt < 2; mt++) {
                uint32_t addr = as_base[buf] +
                    (((wm + mt * 16 + frow) * 72) + kk + fcol) * 2;
                LDSM_X4(a[mt][0], a[mt][1], a[mt][2], a[mt][3], addr);
            }
            uint32_t b[8][2];
#pragma unroll
            for (int np = 0; np < 4; np++) {
                uint32_t addr = bs_base[buf] +
                    (((kk + frow) * 136) + wn + np * 16 + fcol) * 2;
                uint32_t r0, r1, r2, r3;
                LDSM_X4_T(r0, r1, r2, r3, addr);
                b[np * 2 + 0][0] = r0;
                b[np * 2 + 0][1] = r1;
                b[np * 2 + 1][0] = r2;
                b[np * 2 + 1][1] = r3;
            }
#pragma unroll
            for (int mt = 0; mt < 2; mt++)
#pragma unroll
                for (int nt = 0; nt < 8; nt++)
                    mma_f16(acc[mt][nt], a[mt], b[nt][0], b[nt][1]);
        }
        __syncthreads();
    }

#pragma unroll
    for (int mt = 0; mt < 2; mt++) {
#pragma unroll
        for (int nt = 0; nt < 8; nt++) {
            int r0 = bm + wm + mt * 16 + gid;
            int cc = bn + wn + nt * 8 + 2 * tig;
            if (r0 < M_NODES)
                *reinterpret_cast<__half2*>(&C[(size_t)r0 * N_FOUT + cc]) =
                    __floats2half2_rn(acc[mt][nt][0], acc[mt][nt][1]);
            int r1 = r0 + 8;
            if (r1 < M_NODES)
                *reinterpret_cast<__half2*>(&C[(size_t)r1 * N_FOUT + cc]) =
                    __floats2half2_rn(acc[mt][nt][2], acc[mt][nt][3]);
        }
    }
}

// ---------------------------------------------------------------------------
// CSR construction: count -> scan -> scatter (packed int2 payload)
// ---------------------------------------------------------------------------
__global__ __launch_bounds__(256)
void count_kernel(const int* __restrict__ rows)
{
    int idx = blockIdx.x * blockDim.x + threadIdx.x;
    int stride = gridDim.x * blockDim.x;
    for (int e = idx; e < N_EDGES; e += stride) {
        atomicAdd(&g_row_count[rows[e]], 1);
    }
}

#define SCAN_T 1024
__global__ __launch_bounds__(SCAN_T)
void scan_kernel()
{
    __shared__ int part[SCAN_T];
    const int chunk = (M_NODES + SCAN_T - 1) / SCAN_T;
    int t = threadIdx.x;
    int begin = t * chunk;
    int end   = begin + chunk;
    if (end > M_NODES) end = M_NODES;
    if (begin > M_NODES) begin = M_NODES;

    int s = 0;
    for (int i = begin; i < end; i++) s += g_row_count[i];
    part[t] = s;
    __syncthreads();

    for (int off = 1; off < SCAN_T; off <<= 1) {
        int v = 0;
        if (t >= off) v = part[t - off];
        __syncthreads();
        part[t] += v;
        __syncthreads();
    }

    int run = (t == 0) ? 0 : part[t - 1];
    for (int i = begin; i < end; i++) {
        g_row_start[i] = run;
        run += g_row_count[i];
    }
    if (t == SCAN_T - 1) g_row_start[M_NODES] = run;
}

__global__ __launch_bounds__(256)
void scatter_kernel(const int*   __restrict__ rows,
                    const int*   __restrict__ cols,
                    const float* __restrict__ vals)
{
    int idx = blockIdx.x * blockDim.x + threadIdx.x;
    int stride = gridDim.x * blockDim.x;
    for (int e = idx; e < N_EDGES; e += stride) {
        int r = rows[e];
        int pos = g_row_start[r] + atomicAdd(&g_row_fill[r], 1);
        g_csr_cv[pos] = make_int2(cols[e], __float_as_int(vals[e]));
    }
}

// ---------------------------------------------------------------------------
// Kernel 2: CSR SpMM + fused ReLU (one warp per row), fp16 h, packed edges.
// ---------------------------------------------------------------------------
__global__ __launch_bounds__(256)
void spmm_csr_kernel(const __half* __restrict__ h,
                     float*        __restrict__ out)
{
    int warp_global = (blockIdx.x * blockDim.x + threadIdx.x) >> 5;
    int lane = threadIdx.x & 31;
    if (warp_global >= M_NODES) return;

    int row = warp_global;
    int s = g_row_start[row];
    int e = g_row_start[row + 1];

    float acc[8];
#pragma unroll
    for (int i = 0; i < 8; i++) acc[i] = 0.f;

    int i = s;
    for (; i + 4 <= e; i += 4) {
        int2 cv0 = g_csr_cv[i + 0];
        int2 cv1 = g_csr_cv[i + 1];
        int2 cv2 = g_csr_cv[i + 2];
        int2 cv3 = g_csr_cv[i + 3];
        float v0 = __int_as_float(cv0.y), v1 = __int_as_float(cv1.y);
        float v2 = __int_as_float(cv2.y), v3 = __int_as_float(cv3.y);
        uint4 p0 = __ldg(reinterpret_cast<const uint4*>(h + (size_t)cv0.x * N_FOUT) + lane);
        uint4 p1 = __ldg(reinterpret_cast<const uint4*>(h + (size_t)cv1.x * N_FOUT) + lane);
        uint4 p2 = __ldg(reinterpret_cast<const uint4*>(h + (size_t)cv2.x * N_FOUT) + lane);
        uint4 p3 = __ldg(reinterpret_cast<const uint4*>(h + (size_t)cv3.x * N_FOUT) + lane);
        const __half2* q0 = reinterpret_cast<const __half2*>(&p0);
        const __half2* q1 = reinterpret_cast<const __half2*>(&p1);
        const __half2* q2 = reinterpret_cast<const __half2*>(&p2);
        const __half2* q3 = reinterpret_cast<const __half2*>(&p3);
#pragma unroll
        for (int j = 0; j < 4; j++) {
            float2 f0 = __half22float2(q0[j]);
            float2 f1 = __half22float2(q1[j]);
            float2 f2 = __half22float2(q2[j]);
            float2 f3 = __half22float2(q3[j]);
            acc[2 * j + 0] += v0 * f0.x + v1 * f1.x + v2 * f2.x + v3 * f3.x;
            acc[2 * j + 1] += v0 * f0.y + v1 * f1.y + v2 * f2.y + v3 * f3.y;
        }
    }
    for (; i < e; i++) {
        int2 cv = g_csr_cv[i];
        float v = __int_as_float(cv.y);
        uint4 p = __ldg(reinterpret_cast<const uint4*>(h + (size_t)cv.x * N_FOUT) + lane);
        const __half2* q = reinterpret_cast<const __half2*>(&p);
#pragma unroll
        for (int j = 0; j < 4; j++) {
            float2 f = __half22float2(q[j]);
            acc[2 * j + 0] += v * f.x;
            acc[2 * j + 1] += v * f.y;
        }
    }

    float* orow = out + (size_t)row * N_FOUT + lane * 8;
    float4 o0 = make_float4(fmaxf(acc[0], 0.f), fmaxf(acc[1], 0.f),
                            fmaxf(acc[2], 0.f), fmaxf(acc[3], 0.f));
    float4 o1 = make_float4(fmaxf(acc[4], 0.f), fmaxf(acc[5], 0.f),
                            fmaxf(acc[6], 0.f), fmaxf(acc[7], 0.f));
    *reinterpret_cast<float4*>(orow + 0) = o0;
    *reinterpret_cast<float4*>(orow + 4) = o1;
}

// ---------------------------------------------------------------------------
// Launch graph (R15 structure, 3-deep convert->GEMM pipeline):
//  s1: conv_c0 -> GEMM(c0) -> GEMM(c1) -> GEMM(c2) -> [CSR join] SpMM
//  s2: convert_w, CSR build
//  s3: conv_c1 -> conv_c2
// ---------------------------------------------------------------------------
extern "C" void kernel_launch(void* const* d_in, const int* in_sizes, int n_in,
                              void* d_out, int out_size)
{
    const float* x        = (const float*)d_in[0];
    const int*   adj_rows = (const int*)  d_in[1];
    const int*   adj_cols = (const int*)  d_in[2];
    const float* adj_vals = (const float*)d_in[3];
    const float* weight   = (const float*)d_in[4];
    float*       out      = (float*)d_out;

    __half* xh = nullptr;
    __half* wh = nullptr;
    __half* h  = nullptr;
    int*    row_count = nullptr;
    int*    row_fill  = nullptr;
    cudaGetSymbolAddress((void**)&xh, g_xh);
    cudaGetSymbolAddress((void**)&wh, g_wh);
    cudaGetSymbolAddress((void**)&h,  g_h);
    cudaGetSymbolAddress((void**)&row_count, g_row_count);
    cudaGetSymbolAddress((void**)&row_fill, g_row_fill);

    static cudaStream_t s2 = nullptr, s3 = nullptr;
    static cudaEvent_t ev_fork = nullptr, ev_join = nullptr, ev_w = nullptr,
                       ev_x1 = nullptr, ev_x2 = nullptr;
    if (s2 == nullptr) {
        cudaStreamCreateWithFlags(&s2, cudaStreamNonBlocking);
        cudaStreamCreateWithFlags(&s3, cudaStreamNonBlocking);
        cudaEventCreateWithFlags(&ev_fork, cudaEventDisableTiming);
        cudaEventCreateWithFlags(&ev_join, cudaEventDisableTiming);
        cudaEventCreateWithFlags(&ev_w, cudaEventDisableTiming);
        cudaEventCreateWithFlags(&ev_x1, cudaEventDisableTiming);
        cudaEventCreateWithFlags(&ev_x2, cudaEventDisableTiming);
        cudaFuncSetAttribute(hgemm_kernel,
                             cudaFuncAttributeMaxDynamicSharedMemorySize,
                             SMEM_BYTES);
    }

    // elem4 chunk boundaries (rows * K_FIN / 4 = rows * 128)
    const size_t e4_0   = (size_t)ROWS0 * 128;                 // end of chunk0
    const size_t e4_1   = (size_t)(ROWS0 + ROWS1) * 128;       // end of chunk1
    const size_t e4_end = (size_t)M_NODES * 128;               // end of chunk2

    // ---- fork ----
    cudaEventRecord(ev_fork, 0);
    cudaStreamWaitEvent(s2, ev_fork, 0);
    cudaStreamWaitEvent(s3, ev_fork, 0);

    // s2: convert_w then CSR build
    convert_w_kernel<<<64, 256, 0, s2>>>(weight, wh);
    cudaEventRecord(ev_w, s2);
    cudaMemsetAsync(row_count, 0, M_NODES * sizeof(int), s2);
    cudaMemsetAsync(row_fill,  0, M_NODES * sizeof(int), s2);
    count_kernel<<<2048, 256, 0, s2>>>(adj_rows);
    scan_kernel<<<1, SCAN_T, 0, s2>>>();
    scatter_kernel<<<2048, 256, 0, s2>>>(adj_rows, adj_cols, adj_vals);
    cudaEventRecord(ev_join, s2);

    // s3: convert x chunks 1 and 2
    convert_x_chunk_kernel<<<768, 256, 0, s3>>>(x, xh, e4_0, e4_1 - e4_0);
    cudaEventRecord(ev_x1, s3);
    convert_x_chunk_kernel<<<768, 256, 0, s3>>>(x, xh, e4_1, e4_end - e4_1);
    cudaEventRecord(ev_x2, s3);

    // s1: convert x chunk0, then GEMM chunks as converts complete
    convert_x_chunk_kernel<<<768, 256>>>(x, xh, 0, e4_0);
    cudaStreamWaitEvent(0, ev_w, 0);
    dim3 gg0(MB0, N_FOUT / 128);
    hgemm_kernel<<<gg0, 256, SMEM_BYTES>>>(xh, wh, h, 0);
    cudaStreamWaitEvent(0, ev_x1, 0);
    dim3 gg1(MB1, N_FOUT / 128);
    hgemm_kernel<<<gg1, 256, SMEM_BYTES>>>(xh, wh, h, MB0);
    cudaStreamWaitEvent(0, ev_x2, 0);
    dim3 gg2(MB2, N_FOUT / 128);
    hgemm_kernel<<<gg2, 256, SMEM_BYTES>>>(xh, wh, h, MB0 + MB1);

    // ---- join, then SpMM ----
    cudaStreamWaitEvent(0, ev_join, 0);
    int nblocks = (M_NODES * 32 + 255) / 256;
    spmm_csr_kernel<<<nblocks, 256>>>(h, out);
}